// round 2
// baseline (speedup 1.0000x reference)
#include <cuda_runtime.h>
#include <cstdint>

#define NN 50000
#define EE 640000
#define DD 128          // feature dim
#define KK 256          // 2*DD
#define DOUT 128

// ---------------- scratch (static device globals; no allocation) -------------
__device__ float g_mean[(size_t)NN * DD];   // neighbor mean, 25.6 MB
__device__ int   g_row[EE];
__device__ int   g_col[EE];
__device__ int   g_cnt[NN];
__device__ int   g_cursor[NN];
__device__ int   g_rowstart[NN + 1];
__device__ int   g_csr[EE];
__device__ int   g_is64;

// ---------------- 0a) detect index dtype (int32 vs int64) --------------------
// For little-endian int64 with values in [0, 50000), every odd 32-bit word is 0.
// For int32, odd words are random node ids. Deterministic given fixed input.
__global__ void detect_kernel(const int* __restrict__ ei32) {
    if (threadIdx.x == 0 && blockIdx.x == 0) {
        int acc = 0;
        for (int i = 0; i < 512; i++) acc |= ei32[2 * i + 1];
        g_is64 = (acc == 0) ? 1 : 0;
    }
}

// ---------------- 0b) decode edge index into int32 row/col (clamped) ---------
__global__ void decode_kernel(const void* __restrict__ ei) {
    int e = blockIdx.x * blockDim.x + threadIdx.x;
    if (e >= EE) return;
    int r, c;
    if (g_is64) {
        const long long* p = (const long long*)ei;
        r = (int)p[e];
        c = (int)p[(size_t)EE + e];
    } else {
        const int* p = (const int*)ei;
        r = p[e];
        c = p[EE + e];
    }
    // safety clamp — guarantees no OOB downstream even if detection were wrong
    r = min(max(r, 0), NN - 1);
    c = min(max(c, 0), NN - 1);
    g_row[e] = r;
    g_col[e] = c;
}

// ---------------- 1) zero counters ------------------------------------------
__global__ void zero_kernel() {
    int i = blockIdx.x * blockDim.x + threadIdx.x;
    if (i < NN) { g_cnt[i] = 0; g_cursor[i] = 0; }
}

// ---------------- 2) histogram of destination rows --------------------------
__global__ void hist_kernel() {
    int e = blockIdx.x * blockDim.x + threadIdx.x;
    if (e < EE) atomicAdd(&g_cnt[g_row[e]], 1);
}

// ---------------- 3) exclusive scan over 50k counts (single block) ----------
__global__ void scan_kernel() {
    const int T = 1024;
    const int C = (NN + T - 1) / T;   // 49
    int t = threadIdx.x;
    int start = t * C;
    int end = min(start + C, NN);
    int s = 0;
    if (start < NN)
        for (int i = start; i < end; i++) s += g_cnt[i];

    __shared__ int wsum[32];
    int lane = t & 31, w = t >> 5;
    int v = s;
#pragma unroll
    for (int d = 1; d < 32; d <<= 1) {
        int u = __shfl_up_sync(0xffffffffu, v, d);
        if (lane >= d) v += u;
    }
    if (lane == 31) wsum[w] = v;
    __syncthreads();
    if (w == 0) {
        int xv = wsum[lane];
#pragma unroll
        for (int d = 1; d < 32; d <<= 1) {
            int u = __shfl_up_sync(0xffffffffu, xv, d);
            if (lane >= d) xv += u;
        }
        wsum[lane] = xv;
    }
    __syncthreads();
    int excl = v - s + (w > 0 ? wsum[w - 1] : 0);
    if (start < NN) {
        int run = excl;
        for (int i = start; i < end; i++) { g_rowstart[i] = run; run += g_cnt[i]; }
        if (end == NN) g_rowstart[NN] = run;
    }
}

// ---------------- 4) fill CSR column lists ----------------------------------
__global__ void fill_kernel() {
    int e = blockIdx.x * blockDim.x + threadIdx.x;
    if (e < EE) {
        int r = g_row[e];
        int p = atomicAdd(&g_cursor[r], 1);
        g_csr[g_rowstart[r] + p] = g_col[e];
    }
}

// ---------------- 5) warp-per-node gather mean (atomic-free) -----------------
__global__ void aggregate_kernel(const float* __restrict__ x) {
    int gtid = blockIdx.x * blockDim.x + threadIdx.x;
    int node = gtid >> 5;
    int lane = gtid & 31;
    if (node >= NN) return;
    int s0 = g_rowstart[node];
    int s1 = g_rowstart[node + 1];
    float4 acc = make_float4(0.f, 0.f, 0.f, 0.f);
    int c = (s0 < s1) ? g_csr[s0] : 0;
    for (int j = s0; j < s1; j++) {
        int cn = (j + 1 < s1) ? g_csr[j + 1] : 0;   // prefetch next col idx
        float4 v = *(const float4*)(x + (size_t)c * DD + lane * 4);
        acc.x += v.x; acc.y += v.y; acc.z += v.z; acc.w += v.w;
        c = cn;
    }
    float inv = 1.0f / ((float)(s1 - s0) + 1e-8f);
    acc.x *= inv; acc.y *= inv; acc.z *= inv; acc.w *= inv;
    *(float4*)(g_mean + (size_t)node * DD + lane * 4) = acc;
}

// ---------------- 6) fused concat-GEMM + bias + relu -------------------------
// out[n,j] = relu( sum_k A[n,k] * W[j,k] + b[j] ),  A = [x | mean]  (K=256)
#define BM 128
#define BNT 128
#define BKT 16
#define SPAD 4

__global__ __launch_bounds__(256, 2)
void gemm_kernel(const float* __restrict__ x, const float* __restrict__ W,
                 const float* __restrict__ b, float* __restrict__ out) {
    __shared__ float As[BKT][BM + SPAD];
    __shared__ float Ws[BKT][BNT + SPAD];

    int t = threadIdx.x;
    int block_m = blockIdx.x * BM;
    int tr = t >> 2;          // 0..63
    int tk = t & 3;           // 0..3  -> float4 column group
    int tm_idx = t >> 4;      // 0..15
    int tn_idx = t & 15;      // 0..15
    int m0 = tm_idx * 8;
    int n0 = tn_idx * 8;

    float acc[8][8];
#pragma unroll
    for (int i = 0; i < 8; i++)
#pragma unroll
        for (int j = 0; j < 8; j++) acc[i][j] = 0.f;

    for (int k0 = 0; k0 < KK; k0 += BKT) {
        const float* abase = (k0 < DD) ? x : g_mean;
        int kk = k0 & (DD - 1);
        // A tile -> As[k][m] (transposed)
#pragma unroll
        for (int rr = 0; rr < 2; rr++) {
            int row = tr + rr * 64;
            int grow = block_m + row;
            float4 v = make_float4(0.f, 0.f, 0.f, 0.f);
            if (grow < NN)
                v = *(const float4*)(abase + (size_t)grow * DD + kk + tk * 4);
            As[tk * 4 + 0][row] = v.x;
            As[tk * 4 + 1][row] = v.y;
            As[tk * 4 + 2][row] = v.z;
            As[tk * 4 + 3][row] = v.w;
        }
        // W tile -> Ws[k][j] (transposed); W row-major [DOUT][KK]
#pragma unroll
        for (int rr = 0; rr < 2; rr++) {
            int j = tr + rr * 64;
            float4 v = *(const float4*)(W + (size_t)j * KK + k0 + tk * 4);
            Ws[tk * 4 + 0][j] = v.x;
            Ws[tk * 4 + 1][j] = v.y;
            Ws[tk * 4 + 2][j] = v.z;
            Ws[tk * 4 + 3][j] = v.w;
        }
        __syncthreads();
#pragma unroll
        for (int k = 0; k < BKT; k++) {
            float a[8], w[8];
            *(float4*)(a)     = *(const float4*)&As[k][m0];
            *(float4*)(a + 4) = *(const float4*)&As[k][m0 + 4];
            *(float4*)(w)     = *(const float4*)&Ws[k][n0];
            *(float4*)(w + 4) = *(const float4*)&Ws[k][n0 + 4];
#pragma unroll
            for (int i = 0; i < 8; i++)
#pragma unroll
                for (int j = 0; j < 8; j++)
                    acc[i][j] += a[i] * w[j];
        }
        __syncthreads();
    }

    float bias[8];
    *(float4*)(bias)     = *(const float4*)(b + n0);
    *(float4*)(bias + 4) = *(const float4*)(b + n0 + 4);
#pragma unroll
    for (int i = 0; i < 8; i++) {
        int grow = block_m + m0 + i;
        if (grow < NN) {
            float4 o1, o2;
            o1.x = fmaxf(acc[i][0] + bias[0], 0.f);
            o1.y = fmaxf(acc[i][1] + bias[1], 0.f);
            o1.z = fmaxf(acc[i][2] + bias[2], 0.f);
            o1.w = fmaxf(acc[i][3] + bias[3], 0.f);
            o2.x = fmaxf(acc[i][4] + bias[4], 0.f);
            o2.y = fmaxf(acc[i][5] + bias[5], 0.f);
            o2.z = fmaxf(acc[i][6] + bias[6], 0.f);
            o2.w = fmaxf(acc[i][7] + bias[7], 0.f);
            *(float4*)(out + (size_t)grow * DOUT + n0)     = o1;
            *(float4*)(out + (size_t)grow * DOUT + n0 + 4) = o2;
        }
    }
}

// ---------------- launch ------------------------------------------------------
extern "C" void kernel_launch(void* const* d_in, const int* in_sizes, int n_in,
                              void* d_out, int out_size) {
    const float* x   = (const float*)d_in[0];
    const void*  ei  = d_in[1];
    const float* W   = (const float*)d_in[2];
    const float* b   = (const float*)d_in[3];
    float*       out = (float*)d_out;

    detect_kernel<<<1, 32>>>((const int*)ei);
    decode_kernel<<<(EE + 255) / 256, 256>>>(ei);
    zero_kernel<<<(NN + 255) / 256, 256>>>();
    hist_kernel<<<(EE + 255) / 256, 256>>>();
    scan_kernel<<<1, 1024>>>();
    fill_kernel<<<(EE + 255) / 256, 256>>>();
    aggregate_kernel<<<(NN * 32 + 255) / 256, 256>>>(x);
    gemm_kernel<<<(NN + BM - 1) / BM, 256>>>(x, W, b, out);
}

// round 3
// speedup vs baseline: 1.9851x; 1.9851x over previous
#include <cuda_runtime.h>
#include <cuda_bf16.h>
#include <cstdint>

#define NN 50000
#define EE 640000
#define DD 128          // feature dim
#define KK 256          // 2*DD
#define DOUT 128

// ---------------- scratch (static device globals; no allocation) -------------
__device__ float g_Y[(size_t)NN * DD];      // x @ W1^T        (25.6 MB)
__device__ float g_Z[(size_t)NN * DD];      // x @ W2^T        (25.6 MB)
__device__ int   g_row[EE];
__device__ int   g_col[EE];
__device__ int   g_cnt[NN];
__device__ int   g_cursor[NN];
__device__ int   g_rowstart[NN + 1];
__device__ int   g_csr[EE];
__device__ int   g_is64;

// ---------------- 0a) detect index dtype (int32 vs int64) --------------------
__global__ void detect_kernel(const int* __restrict__ ei32) {
    if (threadIdx.x == 0 && blockIdx.x == 0) {
        int acc = 0;
        for (int i = 0; i < 512; i++) acc |= ei32[2 * i + 1];
        g_is64 = (acc == 0) ? 1 : 0;
    }
}

// ---------------- 0b) zero counters ------------------------------------------
__global__ void zero_kernel() {
    int i = blockIdx.x * blockDim.x + threadIdx.x;
    if (i < NN) { g_cnt[i] = 0; g_cursor[i] = 0; }
}

// ---------------- 1) decode edge index + histogram (fused) -------------------
__global__ void decode_hist_kernel(const void* __restrict__ ei) {
    int e = blockIdx.x * blockDim.x + threadIdx.x;
    if (e >= EE) return;
    int r, c;
    if (g_is64) {
        const long long* p = (const long long*)ei;
        r = (int)p[e];
        c = (int)p[(size_t)EE + e];
    } else {
        const int* p = (const int*)ei;
        r = p[e];
        c = p[EE + e];
    }
    r = min(max(r, 0), NN - 1);
    c = min(max(c, 0), NN - 1);
    g_row[e] = r;
    g_col[e] = c;
    atomicAdd(&g_cnt[r], 1);
}

// ---------------- 2) exclusive scan over 50k counts (single block) -----------
__global__ void scan_kernel() {
    const int T = 1024;
    const int C = (NN + T - 1) / T;   // 49
    int t = threadIdx.x;
    int start = t * C;
    int end = min(start + C, NN);
    int s = 0;
    if (start < NN)
        for (int i = start; i < end; i++) s += g_cnt[i];

    __shared__ int wsum[32];
    int lane = t & 31, w = t >> 5;
    int v = s;
#pragma unroll
    for (int d = 1; d < 32; d <<= 1) {
        int u = __shfl_up_sync(0xffffffffu, v, d);
        if (lane >= d) v += u;
    }
    if (lane == 31) wsum[w] = v;
    __syncthreads();
    if (w == 0) {
        int xv = wsum[lane];
#pragma unroll
        for (int d = 1; d < 32; d <<= 1) {
            int u = __shfl_up_sync(0xffffffffu, xv, d);
            if (lane >= d) xv += u;
        }
        wsum[lane] = xv;
    }
    __syncthreads();
    int excl = v - s + (w > 0 ? wsum[w - 1] : 0);
    if (start < NN) {
        int run = excl;
        for (int i = start; i < end; i++) { g_rowstart[i] = run; run += g_cnt[i]; }
        if (end == NN) g_rowstart[NN] = run;
    }
}

// ---------------- 3) fill CSR column lists ------------------------------------
__global__ void fill_kernel() {
    int e = blockIdx.x * blockDim.x + threadIdx.x;
    if (e < EE) {
        int r = g_row[e];
        int p = atomicAdd(&g_cursor[r], 1);
        g_csr[g_rowstart[r] + p] = g_col[e];
    }
}

// ---------------- 4) tensor-core GEMM: [Y|Z] = x @ [W1;W2]^T ------------------
// half = blockIdx.y: 0 -> Y[n,j] = sum_k x[n,k] W[j,k]
//                    1 -> Z[n,j] = sum_k x[n,k] W[j,128+k]
// fp32 emulated via bf16 split: a*b ~= ah*bh + ah*bl + al*bh
#define GM 128
#define GN 128
#define GK 32
#define APAD 2

__device__ __forceinline__ void mma_bf16(float c[4], const uint32_t a[4],
                                         uint32_t b0, uint32_t b1) {
    asm volatile(
        "mma.sync.aligned.m16n8k16.row.col.f32.bf16.bf16.f32 "
        "{%0,%1,%2,%3}, {%4,%5,%6,%7}, {%8,%9}, {%0,%1,%2,%3};"
        : "+f"(c[0]), "+f"(c[1]), "+f"(c[2]), "+f"(c[3])
        : "r"(a[0]), "r"(a[1]), "r"(a[2]), "r"(a[3]), "r"(b0), "r"(b1));
}

__global__ __launch_bounds__(256, 2)
void gemm_kernel(const float* __restrict__ x, const float* __restrict__ W) {
    __shared__ __nv_bfloat16 As_hi[GM][GK + APAD];
    __shared__ __nv_bfloat16 As_lo[GM][GK + APAD];
    __shared__ __nv_bfloat16 Bs_hi[GN][GK + APAD];
    __shared__ __nv_bfloat16 Bs_lo[GN][GK + APAD];

    int t = threadIdx.x;
    int block_m = blockIdx.x * GM;
    int half = blockIdx.y;
    int wid = t >> 5, lane = t & 31;
    int wm = (wid & 3) * 32;     // warp M offset
    int wn = (wid >> 2) * 64;    // warp N offset
    int g = lane >> 2, tig = lane & 3;

    float acc[2][8][4];
#pragma unroll
    for (int mi = 0; mi < 2; mi++)
#pragma unroll
        for (int ni = 0; ni < 8; ni++)
#pragma unroll
            for (int q = 0; q < 4; q++) acc[mi][ni][q] = 0.f;

    const float* wbase = W + (half ? DD : 0);

    for (int k0 = 0; k0 < DD; k0 += GK) {
        // load + split A tile (128 x 32 fp32)
#pragma unroll
        for (int i = 0; i < 4; i++) {
            int lin = t + i * 256;            // float4 index
            int row = lin >> 3;
            int kq = (lin & 7) * 4;
            int grow = block_m + row;
            float4 v = make_float4(0.f, 0.f, 0.f, 0.f);
            if (grow < NN)
                v = *(const float4*)(x + (size_t)grow * DD + k0 + kq);
            float vv[4] = {v.x, v.y, v.z, v.w};
#pragma unroll
            for (int q = 0; q < 4; q++) {
                __nv_bfloat16 h = __float2bfloat16(vv[q]);
                As_hi[row][kq + q] = h;
                As_lo[row][kq + q] = __float2bfloat16(vv[q] - __bfloat162float(h));
            }
        }
        // load + split B tile (128 x 32 fp32): B[j][k] = W[j][half*128 + k]
#pragma unroll
        for (int i = 0; i < 4; i++) {
            int lin = t + i * 256;
            int j = lin >> 3;
            int kq = (lin & 7) * 4;
            float4 v = *(const float4*)(wbase + (size_t)j * KK + k0 + kq);
            float vv[4] = {v.x, v.y, v.z, v.w};
#pragma unroll
            for (int q = 0; q < 4; q++) {
                __nv_bfloat16 h = __float2bfloat16(vv[q]);
                Bs_hi[j][kq + q] = h;
                Bs_lo[j][kq + q] = __float2bfloat16(vv[q] - __bfloat162float(h));
            }
        }
        __syncthreads();

#pragma unroll
        for (int kk = 0; kk < GK; kk += 16) {
            uint32_t ahi[2][4], alo[2][4];
#pragma unroll
            for (int mi = 0; mi < 2; mi++) {
                int r0 = wm + mi * 16 + g;
                int r1 = r0 + 8;
                int c0 = kk + 2 * tig;
                int c1 = c0 + 8;
                ahi[mi][0] = *(const uint32_t*)&As_hi[r0][c0];
                ahi[mi][1] = *(const uint32_t*)&As_hi[r1][c0];
                ahi[mi][2] = *(const uint32_t*)&As_hi[r0][c1];
                ahi[mi][3] = *(const uint32_t*)&As_hi[r1][c1];
                alo[mi][0] = *(const uint32_t*)&As_lo[r0][c0];
                alo[mi][1] = *(const uint32_t*)&As_lo[r1][c0];
                alo[mi][2] = *(const uint32_t*)&As_lo[r0][c1];
                alo[mi][3] = *(const uint32_t*)&As_lo[r1][c1];
            }
#pragma unroll
            for (int ni = 0; ni < 8; ni++) {
                int n = wn + ni * 8 + g;
                int c0 = kk + 2 * tig;
                int c1 = c0 + 8;
                uint32_t bh0 = *(const uint32_t*)&Bs_hi[n][c0];
                uint32_t bh1 = *(const uint32_t*)&Bs_hi[n][c1];
                uint32_t bl0 = *(const uint32_t*)&Bs_lo[n][c0];
                uint32_t bl1 = *(const uint32_t*)&Bs_lo[n][c1];
#pragma unroll
                for (int mi = 0; mi < 2; mi++) {
                    mma_bf16(acc[mi][ni], ahi[mi], bh0, bh1);
                    mma_bf16(acc[mi][ni], ahi[mi], bl0, bl1);
                    mma_bf16(acc[mi][ni], alo[mi], bh0, bh1);
                }
            }
        }
        __syncthreads();
    }

    // epilogue: write fp32 result
    float* outp = half ? g_Z : g_Y;
#pragma unroll
    for (int mi = 0; mi < 2; mi++) {
#pragma unroll
        for (int ni = 0; ni < 8; ni++) {
            int r0 = block_m + wm + mi * 16 + g;
            int r1 = r0 + 8;
            int n = wn + ni * 8 + 2 * tig;
            if (r0 < NN)
                *(float2*)(outp + (size_t)r0 * DD + n) =
                    make_float2(acc[mi][ni][0], acc[mi][ni][1]);
            if (r1 < NN)
                *(float2*)(outp + (size_t)r1 * DD + n) =
                    make_float2(acc[mi][ni][2], acc[mi][ni][3]);
        }
    }
}

// ---------------- 5) fused gather + epilogue ----------------------------------
// out[node] = relu( Y[node] + b + (sum_{c in nbrs} Z[c]) / (cnt + 1e-8) )
__global__ void final_kernel(const float* __restrict__ b, float* __restrict__ out) {
    int gtid = blockIdx.x * blockDim.x + threadIdx.x;
    int node = gtid >> 5;
    int lane = gtid & 31;
    if (node >= NN) return;
    int s0 = g_rowstart[node];
    int s1 = g_rowstart[node + 1];
    float4 acc = make_float4(0.f, 0.f, 0.f, 0.f);
    int c = (s0 < s1) ? g_csr[s0] : 0;
    for (int j = s0; j < s1; j++) {
        int cn = (j + 1 < s1) ? g_csr[j + 1] : 0;   // prefetch next col idx
        float4 v = *(const float4*)(g_Z + (size_t)c * DD + lane * 4);
        acc.x += v.x; acc.y += v.y; acc.z += v.z; acc.w += v.w;
        c = cn;
    }
    float inv = 1.0f / ((float)(s1 - s0) + 1e-8f);
    float4 y  = *(const float4*)(g_Y + (size_t)node * DD + lane * 4);
    float4 bb = *(const float4*)(b + lane * 4);
    float4 o;
    o.x = fmaxf(y.x + bb.x + acc.x * inv, 0.f);
    o.y = fmaxf(y.y + bb.y + acc.y * inv, 0.f);
    o.z = fmaxf(y.z + bb.z + acc.z * inv, 0.f);
    o.w = fmaxf(y.w + bb.w + acc.w * inv, 0.f);
    *(float4*)(out + (size_t)node * DD + lane * 4) = o;
}

// ---------------- launch ------------------------------------------------------
extern "C" void kernel_launch(void* const* d_in, const int* in_sizes, int n_in,
                              void* d_out, int out_size) {
    const float* x   = (const float*)d_in[0];
    const void*  ei  = d_in[1];
    const float* W   = (const float*)d_in[2];
    const float* b   = (const float*)d_in[3];
    float*       out = (float*)d_out;

    detect_kernel<<<1, 32>>>((const int*)ei);
    zero_kernel<<<(NN + 255) / 256, 256>>>();
    decode_hist_kernel<<<(EE + 255) / 256, 256>>>(ei);
    scan_kernel<<<1, 1024>>>();
    fill_kernel<<<(EE + 255) / 256, 256>>>();
    dim3 ggrid((NN + GM - 1) / GM, 2);
    gemm_kernel<<<ggrid, 256>>>(x, W);
    final_kernel<<<(NN * 32 + 255) / 256, 256>>>(b, out);
}

// round 4
// speedup vs baseline: 2.7542x; 1.3874x over previous
#include <cuda_runtime.h>
#include <cuda_bf16.h>
#include <cstdint>

#define NN 50000
#define EE 640000
#define DD 128          // feature dim
#define KK 256          // 2*DD
#define DOUT 128
#define NBLK 196        // ceil(NN/256)

// ---------------- scratch (static device globals; no allocation) -------------
__device__ float g_Y[(size_t)NN * DD];      // x @ W1^T        (25.6 MB)
__device__ float g_Z[(size_t)NN * DD];      // x @ W2^T        (25.6 MB)
__device__ int   g_row[EE];
__device__ int   g_col[EE];
__device__ int   g_cnt[NN];
__device__ int   g_cursor[NN];
__device__ int   g_rowstart[NN + 1];
__device__ int   g_csr[EE];
__device__ int   g_partial[256];
__device__ int   g_is64;

// ---------------- 0a) detect index dtype (int32 vs int64) --------------------
// For little-endian int64 with values in [0, 50000), every odd 32-bit word is 0.
__global__ void detect_kernel(const int* __restrict__ ei32) {
    int t = threadIdx.x;
    int acc = 0;
    for (int i = t; i < 512; i += 32) acc |= ei32[2 * i + 1];
#pragma unroll
    for (int d = 16; d; d >>= 1) acc |= __shfl_xor_sync(0xffffffffu, acc, d);
    if (t == 0) g_is64 = (acc == 0) ? 1 : 0;
}

// ---------------- 0b) zero counters ------------------------------------------
__global__ void zero_kernel() {
    int i = blockIdx.x * blockDim.x + threadIdx.x;
    if (i < NN) { g_cnt[i] = 0; g_cursor[i] = 0; }
}

// ---------------- 1) decode edge index + histogram (fused) -------------------
__global__ void decode_hist_kernel(const void* __restrict__ ei) {
    int e = blockIdx.x * blockDim.x + threadIdx.x;
    if (e >= EE) return;
    int r, c;
    if (g_is64) {
        const long long* p = (const long long*)ei;
        r = (int)p[e];
        c = (int)p[(size_t)EE + e];
    } else {
        const int* p = (const int*)ei;
        r = p[e];
        c = p[EE + e];
    }
    r = min(max(r, 0), NN - 1);
    c = min(max(c, 0), NN - 1);
    g_row[e] = r;
    g_col[e] = c;
    atomicAdd(&g_cnt[r], 1);
}

// ---------------- 2) three-phase exclusive scan (whole chip) ------------------
// 2a: per-block reduction of 256 counts
__global__ void scanA_kernel() {
    __shared__ int red[8];
    int b = blockIdx.x, t = threadIdx.x;
    int i = b * 256 + t;
    int v = (i < NN) ? g_cnt[i] : 0;
#pragma unroll
    for (int d = 16; d; d >>= 1) v += __shfl_down_sync(0xffffffffu, v, d);
    if ((t & 31) == 0) red[t >> 5] = v;
    __syncthreads();
    if (t < 8) {
        int s = red[t];
#pragma unroll
        for (int d = 4; d; d >>= 1) s += __shfl_down_sync(0xffu, s, d);
        if (t == 0) g_partial[b] = s;
    }
}

// 2b: scan the 196 block sums -> exclusive block offsets
__global__ void scanB_kernel() {
    __shared__ int ws[8];
    int t = threadIdx.x;
    int v = (t < NBLK) ? g_partial[t] : 0;
    int lane = t & 31, w = t >> 5;
    int xv = v;
#pragma unroll
    for (int d = 1; d < 32; d <<= 1) {
        int u = __shfl_up_sync(0xffffffffu, xv, d);
        if (lane >= d) xv += u;
    }
    if (lane == 31) ws[w] = xv;
    __syncthreads();
    if (w == 0 && lane < 8) {
        int y = ws[lane];
#pragma unroll
        for (int d = 1; d < 8; d <<= 1) {
            int u = __shfl_up_sync(0xffu, y, d);
            if (lane >= d) y += u;
        }
        ws[lane] = y;
    }
    __syncthreads();
    int incl = xv + (w ? ws[w - 1] : 0);
    if (t < NBLK) g_partial[t] = incl - v;   // exclusive offset per block
    if (t == 0) g_rowstart[NN] = EE;
}

// 2c: in-block exclusive scan + block offset -> rowstart
__global__ void scanC_kernel() {
    __shared__ int ws[8];
    int b = blockIdx.x, t = threadIdx.x;
    int i = b * 256 + t;
    int v = (i < NN) ? g_cnt[i] : 0;
    int lane = t & 31, w = t >> 5;
    int xv = v;
#pragma unroll
    for (int d = 1; d < 32; d <<= 1) {
        int u = __shfl_up_sync(0xffffffffu, xv, d);
        if (lane >= d) xv += u;
    }
    if (lane == 31) ws[w] = xv;
    __syncthreads();
    if (w == 0 && lane < 8) {
        int y = ws[lane];
#pragma unroll
        for (int d = 1; d < 8; d <<= 1) {
            int u = __shfl_up_sync(0xffu, y, d);
            if (lane >= d) y += u;
        }
        ws[lane] = y;
    }
    __syncthreads();
    int excl = xv - v + (w ? ws[w - 1] : 0) + g_partial[b];
    if (i < NN) g_rowstart[i] = excl;
}

// ---------------- 3) fill CSR column lists ------------------------------------
__global__ void fill_kernel() {
    int e = blockIdx.x * blockDim.x + threadIdx.x;
    if (e < EE) {
        int r = g_row[e];
        int p = atomicAdd(&g_cursor[r], 1);
        g_csr[g_rowstart[r] + p] = g_col[e];
    }
}

// ---------------- 4) tensor-core GEMM: [Y|Z] = x @ [W1;W2]^T ------------------
// half = blockIdx.y: 0 -> Y[n,j] = sum_k x[n,k] W[j,k]
//                    1 -> Z[n,j] = sum_k x[n,k] W[j,128+k]
// fp32 emulated via bf16 split: a*b ~= ah*bh + ah*bl + al*bh
#define GM 128
#define GN 128
#define GK 32
#define APAD 2

__device__ __forceinline__ void mma_bf16(float c[4], const uint32_t a[4],
                                         uint32_t b0, uint32_t b1) {
    asm volatile(
        "mma.sync.aligned.m16n8k16.row.col.f32.bf16.bf16.f32 "
        "{%0,%1,%2,%3}, {%4,%5,%6,%7}, {%8,%9}, {%0,%1,%2,%3};"
        : "+f"(c[0]), "+f"(c[1]), "+f"(c[2]), "+f"(c[3])
        : "r"(a[0]), "r"(a[1]), "r"(a[2]), "r"(a[3]), "r"(b0), "r"(b1));
}

__global__ __launch_bounds__(256, 2)
void gemm_kernel(const float* __restrict__ x, const float* __restrict__ W) {
    __shared__ __nv_bfloat16 As_hi[GM][GK + APAD];
    __shared__ __nv_bfloat16 As_lo[GM][GK + APAD];
    __shared__ __nv_bfloat16 Bs_hi[GN][GK + APAD];
    __shared__ __nv_bfloat16 Bs_lo[GN][GK + APAD];

    int t = threadIdx.x;
    int block_m = blockIdx.x * GM;
    int half = blockIdx.y;
    int wid = t >> 5, lane = t & 31;
    int wm = (wid & 3) * 32;     // warp M offset
    int wn = (wid >> 2) * 64;    // warp N offset
    int g = lane >> 2, tig = lane & 3;

    float acc[2][8][4];
#pragma unroll
    for (int mi = 0; mi < 2; mi++)
#pragma unroll
        for (int ni = 0; ni < 8; ni++)
#pragma unroll
            for (int q = 0; q < 4; q++) acc[mi][ni][q] = 0.f;

    const float* wbase = W + (half ? DD : 0);

    for (int k0 = 0; k0 < DD; k0 += GK) {
        // load + split A tile (128 x 32 fp32)
#pragma unroll
        for (int i = 0; i < 4; i++) {
            int lin = t + i * 256;            // float4 index
            int row = lin >> 3;
            int kq = (lin & 7) * 4;
            int grow = block_m + row;
            float4 v = make_float4(0.f, 0.f, 0.f, 0.f);
            if (grow < NN)
                v = *(const float4*)(x + (size_t)grow * DD + k0 + kq);
            float vv[4] = {v.x, v.y, v.z, v.w};
#pragma unroll
            for (int q = 0; q < 4; q++) {
                __nv_bfloat16 h = __float2bfloat16(vv[q]);
                As_hi[row][kq + q] = h;
                As_lo[row][kq + q] = __float2bfloat16(vv[q] - __bfloat162float(h));
            }
        }
        // load + split B tile (128 x 32 fp32): B[j][k] = W[j][half*128 + k]
#pragma unroll
        for (int i = 0; i < 4; i++) {
            int lin = t + i * 256;
            int j = lin >> 3;
            int kq = (lin & 7) * 4;
            float4 v = *(const float4*)(wbase + (size_t)j * KK + k0 + kq);
            float vv[4] = {v.x, v.y, v.z, v.w};
#pragma unroll
            for (int q = 0; q < 4; q++) {
                __nv_bfloat16 h = __float2bfloat16(vv[q]);
                Bs_hi[j][kq + q] = h;
                Bs_lo[j][kq + q] = __float2bfloat16(vv[q] - __bfloat162float(h));
            }
        }
        __syncthreads();

#pragma unroll
        for (int kk = 0; kk < GK; kk += 16) {
            uint32_t ahi[2][4], alo[2][4];
#pragma unroll
            for (int mi = 0; mi < 2; mi++) {
                int r0 = wm + mi * 16 + g;
                int r1 = r0 + 8;
                int c0 = kk + 2 * tig;
                int c1 = c0 + 8;
                ahi[mi][0] = *(const uint32_t*)&As_hi[r0][c0];
                ahi[mi][1] = *(const uint32_t*)&As_hi[r1][c0];
                ahi[mi][2] = *(const uint32_t*)&As_hi[r0][c1];
                ahi[mi][3] = *(const uint32_t*)&As_hi[r1][c1];
                alo[mi][0] = *(const uint32_t*)&As_lo[r0][c0];
                alo[mi][1] = *(const uint32_t*)&As_lo[r1][c0];
                alo[mi][2] = *(const uint32_t*)&As_lo[r0][c1];
                alo[mi][3] = *(const uint32_t*)&As_lo[r1][c1];
            }
#pragma unroll
            for (int ni = 0; ni < 8; ni++) {
                int n = wn + ni * 8 + g;
                int c0 = kk + 2 * tig;
                int c1 = c0 + 8;
                uint32_t bh0 = *(const uint32_t*)&Bs_hi[n][c0];
                uint32_t bh1 = *(const uint32_t*)&Bs_hi[n][c1];
                uint32_t bl0 = *(const uint32_t*)&Bs_lo[n][c0];
                uint32_t bl1 = *(const uint32_t*)&Bs_lo[n][c1];
#pragma unroll
                for (int mi = 0; mi < 2; mi++) {
                    mma_bf16(acc[mi][ni], ahi[mi], bh0, bh1);
                    mma_bf16(acc[mi][ni], ahi[mi], bl0, bl1);
                    mma_bf16(acc[mi][ni], alo[mi], bh0, bh1);
                }
            }
        }
        __syncthreads();
    }

    // epilogue: write fp32 result
    float* outp = half ? g_Z : g_Y;
#pragma unroll
    for (int mi = 0; mi < 2; mi++) {
#pragma unroll
        for (int ni = 0; ni < 8; ni++) {
            int r0 = block_m + wm + mi * 16 + g;
            int r1 = r0 + 8;
            int n = wn + ni * 8 + 2 * tig;
            if (r0 < NN)
                *(float2*)(outp + (size_t)r0 * DD + n) =
                    make_float2(acc[mi][ni][0], acc[mi][ni][1]);
            if (r1 < NN)
                *(float2*)(outp + (size_t)r1 * DD + n) =
                    make_float2(acc[mi][ni][2], acc[mi][ni][3]);
        }
    }
}

// ---------------- 5) fused gather + epilogue ----------------------------------
// out[node] = relu( Y[node] + b + (sum_{c in nbrs} Z[c]) / (cnt + 1e-8) )
__global__ void final_kernel(const float* __restrict__ b, float* __restrict__ out) {
    int gtid = blockIdx.x * blockDim.x + threadIdx.x;
    int node = gtid >> 5;
    int lane = gtid & 31;
    if (node >= NN) return;
    int s0 = g_rowstart[node];
    int s1 = g_rowstart[node + 1];
    float4 acc = make_float4(0.f, 0.f, 0.f, 0.f);
    int c = (s0 < s1) ? g_csr[s0] : 0;
    for (int j = s0; j < s1; j++) {
        int cn = (j + 1 < s1) ? g_csr[j + 1] : 0;   // prefetch next col idx
        float4 v = *(const float4*)(g_Z + (size_t)c * DD + lane * 4);
        acc.x += v.x; acc.y += v.y; acc.z += v.z; acc.w += v.w;
        c = cn;
    }
    float inv = 1.0f / ((float)(s1 - s0) + 1e-8f);
    float4 y  = *(const float4*)(g_Y + (size_t)node * DD + lane * 4);
    float4 bb = *(const float4*)(b + lane * 4);
    float4 o;
    o.x = fmaxf(y.x + bb.x + acc.x * inv, 0.f);
    o.y = fmaxf(y.y + bb.y + acc.y * inv, 0.f);
    o.z = fmaxf(y.z + bb.z + acc.z * inv, 0.f);
    o.w = fmaxf(y.w + bb.w + acc.w * inv, 0.f);
    *(float4*)(out + (size_t)node * DOUT + lane * 4) = o;
}

// ---------------- launch ------------------------------------------------------
extern "C" void kernel_launch(void* const* d_in, const int* in_sizes, int n_in,
                              void* d_out, int out_size) {
    const float* x   = (const float*)d_in[0];
    const void*  ei  = d_in[1];
    const float* W   = (const float*)d_in[2];
    const float* b   = (const float*)d_in[3];
    float*       out = (float*)d_out;

    detect_kernel<<<1, 32>>>((const int*)ei);
    zero_kernel<<<(NN + 255) / 256, 256>>>();
    decode_hist_kernel<<<(EE + 255) / 256, 256>>>(ei);
    scanA_kernel<<<NBLK, 256>>>();
    scanB_kernel<<<1, 256>>>();
    scanC_kernel<<<NBLK, 256>>>();
    fill_kernel<<<(EE + 255) / 256, 256>>>();
    dim3 ggrid((NN + GM - 1) / GM, 2);
    gemm_kernel<<<ggrid, 256>>>(x, W);
    final_kernel<<<(NN * 32 + 255) / 256, 256>>>(b, out);
}

// round 5
// speedup vs baseline: 3.4035x; 1.2357x over previous
#include <cuda_runtime.h>
#include <cuda_bf16.h>
#include <cstdint>

#define NN 50000
#define EE 640000
#define DD 128          // feature dim
#define KK 256          // 2*DD
#define DOUT 128
#define NBLK 196        // ceil(NN/256)

// ---------------- scratch (static device globals; no allocation) -------------
__device__ float g_Y[(size_t)NN * DD];      // x @ W1^T        (25.6 MB)
__device__ float g_Z[(size_t)NN * DD];      // x @ W2^T        (25.6 MB)
__device__ int   g_row[EE];
__device__ int   g_col[EE];
__device__ int   g_cnt[NN];
__device__ int   g_cursor[NN];              // becomes absolute write cursor
__device__ int   g_rowstart[NN + 1];
__device__ int   g_csr[EE];
__device__ int   g_partial[256];

// ---------------- 0) zero counters -------------------------------------------
__global__ void zero_kernel() {
    int i = blockIdx.x * blockDim.x + threadIdx.x;
    if (i < NN) g_cnt[i] = 0;
}

// ---------------- 1) decode edge index + histogram (inline dtype detect) -----
// int64 little-endian with values < 50000 => odd 32-bit words all zero.
__global__ void decode_hist_kernel(const void* __restrict__ ei) {
    const int* ei32 = (const int*)ei;
    int t = threadIdx.x;
    int accw = ei32[2 * t + 1] | ei32[2 * (t + 256) + 1];
    int is32 = __syncthreads_or(accw);      // nonzero -> int32 indices

    int e = blockIdx.x * blockDim.x + t;
    if (e >= EE) return;
    int r, c;
    if (!is32) {
        const long long* p = (const long long*)ei;
        r = (int)p[e];
        c = (int)p[(size_t)EE + e];
    } else {
        r = ei32[e];
        c = ei32[EE + e];
    }
    r = min(max(r, 0), NN - 1);
    c = min(max(c, 0), NN - 1);
    g_row[e] = r;
    g_col[e] = c;
    atomicAdd(&g_cnt[r], 1);
}

// ---------------- 2a: per-block reduction of 256 counts ----------------------
__global__ void scanA_kernel() {
    __shared__ int red[8];
    int b = blockIdx.x, t = threadIdx.x;
    int i = b * 256 + t;
    int v = (i < NN) ? g_cnt[i] : 0;
#pragma unroll
    for (int d = 16; d; d >>= 1) v += __shfl_down_sync(0xffffffffu, v, d);
    if ((t & 31) == 0) red[t >> 5] = v;
    __syncthreads();
    if (t < 8) {
        int s = red[t];
#pragma unroll
        for (int d = 4; d; d >>= 1) s += __shfl_down_sync(0xffu, s, d);
        if (t == 0) g_partial[b] = s;
    }
}

// ---------------- 2b: full scan (partials scanned redundantly per block) -----
__global__ void scanC_kernel() {
    __shared__ int ws[8];
    __shared__ int spart[NBLK];
    int b = blockIdx.x, t = threadIdx.x;
    int lane = t & 31, w = t >> 5;

    // phase 1: exclusive scan of the 196 block sums (every block does it)
    {
        int pv = (t < NBLK) ? g_partial[t] : 0;
        int xv = pv;
#pragma unroll
        for (int d = 1; d < 32; d <<= 1) {
            int u = __shfl_up_sync(0xffffffffu, xv, d);
            if (lane >= d) xv += u;
        }
        if (lane == 31) ws[w] = xv;
        __syncthreads();
        if (w == 0 && lane < 8) {
            int y = ws[lane];
#pragma unroll
            for (int d = 1; d < 8; d <<= 1) {
                int u = __shfl_up_sync(0xffu, y, d);
                if (lane >= d) y += u;
            }
            ws[lane] = y;
        }
        __syncthreads();
        int pincl = xv + (w ? ws[w - 1] : 0);
        if (t < NBLK) spart[t] = pincl - pv;
        __syncthreads();
    }

    // phase 2: in-block exclusive scan of counts + block offset
    int i = b * 256 + t;
    int v = (i < NN) ? g_cnt[i] : 0;
    int xv = v;
#pragma unroll
    for (int d = 1; d < 32; d <<= 1) {
        int u = __shfl_up_sync(0xffffffffu, xv, d);
        if (lane >= d) xv += u;
    }
    if (lane == 31) ws[w] = xv;
    __syncthreads();
    if (w == 0 && lane < 8) {
        int y = ws[lane];
#pragma unroll
        for (int d = 1; d < 8; d <<= 1) {
            int u = __shfl_up_sync(0xffu, y, d);
            if (lane >= d) y += u;
        }
        ws[lane] = y;
    }
    __syncthreads();
    int excl = xv - v + (w ? ws[w - 1] : 0) + spart[b];
    if (i < NN) {
        g_rowstart[i] = excl;
        g_cursor[i]   = excl;   // absolute cursor for fill
    }
    if (b == 0 && t == 0) g_rowstart[NN] = EE;
}

// ---------------- 3) fill CSR column lists ------------------------------------
__global__ void fill_kernel() {
    int e = blockIdx.x * blockDim.x + threadIdx.x;
    if (e < EE) {
        int p = atomicAdd(&g_cursor[g_row[e]], 1);
        g_csr[p] = g_col[e];
    }
}

// ---------------- 4) tensor-core GEMM: [Y|Z] = x @ [W1;W2]^T ------------------
// fp32 emulated via bf16 split: a*b ~= ah*bh + ah*bl + al*bh
#define GM 128
#define GN 128
#define GK 32
#define APAD 2

__device__ __forceinline__ void mma_bf16(float c[4], const uint32_t a[4],
                                         uint32_t b0, uint32_t b1) {
    asm volatile(
        "mma.sync.aligned.m16n8k16.row.col.f32.bf16.bf16.f32 "
        "{%0,%1,%2,%3}, {%4,%5,%6,%7}, {%8,%9}, {%0,%1,%2,%3};"
        : "+f"(c[0]), "+f"(c[1]), "+f"(c[2]), "+f"(c[3])
        : "r"(a[0]), "r"(a[1]), "r"(a[2]), "r"(a[3]), "r"(b0), "r"(b1));
}

__global__ __launch_bounds__(256, 2)
void gemm_kernel(const float* __restrict__ x, const float* __restrict__ W) {
    __shared__ __nv_bfloat16 As_hi[GM][GK + APAD];
    __shared__ __nv_bfloat16 As_lo[GM][GK + APAD];
    __shared__ __nv_bfloat16 Bs_hi[GN][GK + APAD];
    __shared__ __nv_bfloat16 Bs_lo[GN][GK + APAD];

    int t = threadIdx.x;
    int block_m = blockIdx.x * GM;
    int half = blockIdx.y;
    int wid = t >> 5, lane = t & 31;
    int wm = (wid & 3) * 32;     // warp M offset
    int wn = (wid >> 2) * 64;    // warp N offset
    int g = lane >> 2, tig = lane & 3;

    float acc[2][8][4];
#pragma unroll
    for (int mi = 0; mi < 2; mi++)
#pragma unroll
        for (int ni = 0; ni < 8; ni++)
#pragma unroll
            for (int q = 0; q < 4; q++) acc[mi][ni][q] = 0.f;

    const float* wbase = W + (half ? DD : 0);

    for (int k0 = 0; k0 < DD; k0 += GK) {
#pragma unroll
        for (int i = 0; i < 4; i++) {
            int lin = t + i * 256;            // float4 index
            int row = lin >> 3;
            int kq = (lin & 7) * 4;
            int grow = block_m + row;
            float4 v = make_float4(0.f, 0.f, 0.f, 0.f);
            if (grow < NN)
                v = *(const float4*)(x + (size_t)grow * DD + k0 + kq);
            float vv[4] = {v.x, v.y, v.z, v.w};
#pragma unroll
            for (int q = 0; q < 4; q++) {
                __nv_bfloat16 h = __float2bfloat16(vv[q]);
                As_hi[row][kq + q] = h;
                As_lo[row][kq + q] = __float2bfloat16(vv[q] - __bfloat162float(h));
            }
        }
#pragma unroll
        for (int i = 0; i < 4; i++) {
            int lin = t + i * 256;
            int j = lin >> 3;
            int kq = (lin & 7) * 4;
            float4 v = *(const float4*)(wbase + (size_t)j * KK + k0 + kq);
            float vv[4] = {v.x, v.y, v.z, v.w};
#pragma unroll
            for (int q = 0; q < 4; q++) {
                __nv_bfloat16 h = __float2bfloat16(vv[q]);
                Bs_hi[j][kq + q] = h;
                Bs_lo[j][kq + q] = __float2bfloat16(vv[q] - __bfloat162float(h));
            }
        }
        __syncthreads();

#pragma unroll
        for (int kk = 0; kk < GK; kk += 16) {
            uint32_t ahi[2][4], alo[2][4];
#pragma unroll
            for (int mi = 0; mi < 2; mi++) {
                int r0 = wm + mi * 16 + g;
                int r1 = r0 + 8;
                int c0 = kk + 2 * tig;
                int c1 = c0 + 8;
                ahi[mi][0] = *(const uint32_t*)&As_hi[r0][c0];
                ahi[mi][1] = *(const uint32_t*)&As_hi[r1][c0];
                ahi[mi][2] = *(const uint32_t*)&As_hi[r0][c1];
                ahi[mi][3] = *(const uint32_t*)&As_hi[r1][c1];
                alo[mi][0] = *(const uint32_t*)&As_lo[r0][c0];
                alo[mi][1] = *(const uint32_t*)&As_lo[r1][c0];
                alo[mi][2] = *(const uint32_t*)&As_lo[r0][c1];
                alo[mi][3] = *(const uint32_t*)&As_lo[r1][c1];
            }
#pragma unroll
            for (int ni = 0; ni < 8; ni++) {
                int n = wn + ni * 8 + g;
                int c0 = kk + 2 * tig;
                int c1 = c0 + 8;
                uint32_t bh0 = *(const uint32_t*)&Bs_hi[n][c0];
                uint32_t bh1 = *(const uint32_t*)&Bs_hi[n][c1];
                uint32_t bl0 = *(const uint32_t*)&Bs_lo[n][c0];
                uint32_t bl1 = *(const uint32_t*)&Bs_lo[n][c1];
#pragma unroll
                for (int mi = 0; mi < 2; mi++) {
                    mma_bf16(acc[mi][ni], ahi[mi], bh0, bh1);
                    mma_bf16(acc[mi][ni], ahi[mi], bl0, bl1);
                    mma_bf16(acc[mi][ni], alo[mi], bh0, bh1);
                }
            }
        }
        __syncthreads();
    }

    float* outp = half ? g_Z : g_Y;
#pragma unroll
    for (int mi = 0; mi < 2; mi++) {
#pragma unroll
        for (int ni = 0; ni < 8; ni++) {
            int r0 = block_m + wm + mi * 16 + g;
            int r1 = r0 + 8;
            int n = wn + ni * 8 + 2 * tig;
            if (r0 < NN)
                *(float2*)(outp + (size_t)r0 * DD + n) =
                    make_float2(acc[mi][ni][0], acc[mi][ni][1]);
            if (r1 < NN)
                *(float2*)(outp + (size_t)r1 * DD + n) =
                    make_float2(acc[mi][ni][2], acc[mi][ni][3]);
        }
    }
}

// ---------------- 5) fused gather + epilogue ----------------------------------
__global__ void final_kernel(const float* __restrict__ b, float* __restrict__ out) {
    int gtid = blockIdx.x * blockDim.x + threadIdx.x;
    int node = gtid >> 5;
    int lane = gtid & 31;
    if (node >= NN) return;
    int s0 = g_rowstart[node];
    int s1 = g_rowstart[node + 1];
    float4 acc = make_float4(0.f, 0.f, 0.f, 0.f);
    int c = (s0 < s1) ? g_csr[s0] : 0;
    for (int j = s0; j < s1; j++) {
        int cn = (j + 1 < s1) ? g_csr[j + 1] : 0;
        float4 v = *(const float4*)(g_Z + (size_t)c * DD + lane * 4);
        acc.x += v.x; acc.y += v.y; acc.z += v.z; acc.w += v.w;
        c = cn;
    }
    float inv = 1.0f / ((float)(s1 - s0) + 1e-8f);
    float4 y  = *(const float4*)(g_Y + (size_t)node * DD + lane * 4);
    float4 bb = *(const float4*)(b + lane * 4);
    float4 o;
    o.x = fmaxf(y.x + bb.x + acc.x * inv, 0.f);
    o.y = fmaxf(y.y + bb.y + acc.y * inv, 0.f);
    o.z = fmaxf(y.z + bb.z + acc.z * inv, 0.f);
    o.w = fmaxf(y.w + bb.w + acc.w * inv, 0.f);
    *(float4*)(out + (size_t)node * DOUT + lane * 4) = o;
}

// ---------------- launch ------------------------------------------------------
// Fork: CSR build (side stream) runs concurrently with the GEMM (main stream);
// join before the final gather. kernel_launch is only called a handful of times
// (correctness + capture) — replays re-execute the captured graph — so the
// per-call stream/event handles are simply leaked (no device memory involved).
extern "C" void kernel_launch(void* const* d_in, const int* in_sizes, int n_in,
                              void* d_out, int out_size) {
    const float* x   = (const float*)d_in[0];
    const void*  ei  = d_in[1];
    const float* W   = (const float*)d_in[2];
    const float* b   = (const float*)d_in[3];
    float*       out = (float*)d_out;

    cudaStream_t s1;
    cudaEvent_t  e_fork, e_join;
    cudaStreamCreateWithFlags(&s1, cudaStreamNonBlocking);
    cudaEventCreateWithFlags(&e_fork, cudaEventDisableTiming);
    cudaEventCreateWithFlags(&e_join, cudaEventDisableTiming);

    // fork
    cudaEventRecord(e_fork, 0);
    cudaStreamWaitEvent(s1, e_fork, 0);

    // CSR branch (side stream)
    zero_kernel<<<(NN + 255) / 256, 256, 0, s1>>>();
    decode_hist_kernel<<<(EE + 255) / 256, 256, 0, s1>>>(ei);
    scanA_kernel<<<NBLK, 256, 0, s1>>>();
    scanC_kernel<<<NBLK, 256, 0, s1>>>();
    fill_kernel<<<(EE + 255) / 256, 256, 0, s1>>>();
    cudaEventRecord(e_join, s1);

    // GEMM branch (main stream) — overlaps CSR build
    dim3 ggrid((NN + GM - 1) / GM, 2);
    gemm_kernel<<<ggrid, 256>>>(x, W);

    // join + final
    cudaStreamWaitEvent(0, e_join, 0);
    final_kernel<<<(NN * 32 + 255) / 256, 256>>>(b, out);
}

// round 6
// speedup vs baseline: 3.6491x; 1.0722x over previous
#include <cuda_runtime.h>
#include <cuda_bf16.h>
#include <cuda_fp16.h>
#include <cstdint>

#define NN 50000
#define EE 640000
#define DD 128          // feature dim
#define KK 256          // 2*DD
#define DOUT 128
#define NBLK 196        // ceil(NN/256)

// ---------------- scratch (static device globals; no allocation) -------------
__device__ float  g_Y[(size_t)NN * DD];     // x @ W1^T   fp32 (25.6 MB)
__device__ __half g_Z[(size_t)NN * DD];     // x @ W2^T   fp16 (12.8 MB)
__device__ int    g_row[EE];
__device__ int    g_col[EE];
__device__ int    g_slot[EE];               // per-edge slot within its row
__device__ int    g_cnt[NN];
__device__ int    g_rowstart[NN + 1];
__device__ int    g_csr[EE];
__device__ int    g_partial[256];

// ---------------- 0) zero counters -------------------------------------------
__global__ void zero_kernel() {
    int i = blockIdx.x * blockDim.x + threadIdx.x;
    if (i < NN) g_cnt[i] = 0;
}

// ---------------- 1) decode edge index + histogram + slot (fused) ------------
// int64 little-endian with values < 50000 => odd 32-bit words all zero.
__global__ void decode_hist_kernel(const void* __restrict__ ei) {
    const int* ei32 = (const int*)ei;
    int t = threadIdx.x;
    int accw = ei32[2 * t + 1] | ei32[2 * (t + 256) + 1];
    int is32 = __syncthreads_or(accw);      // nonzero -> int32 indices

    int e = blockIdx.x * blockDim.x + t;
    if (e >= EE) return;
    int r, c;
    if (!is32) {
        const long long* p = (const long long*)ei;
        r = (int)p[e];
        c = (int)p[(size_t)EE + e];
    } else {
        r = ei32[e];
        c = ei32[EE + e];
    }
    r = min(max(r, 0), NN - 1);
    c = min(max(c, 0), NN - 1);
    g_row[e] = r;
    g_col[e] = c;
    g_slot[e] = atomicAdd(&g_cnt[r], 1);    // histogram + slot in one atomic
}

// ---------------- 2a: per-block reduction of 256 counts ----------------------
__global__ void scanA_kernel() {
    __shared__ int red[8];
    int b = blockIdx.x, t = threadIdx.x;
    int i = b * 256 + t;
    int v = (i < NN) ? g_cnt[i] : 0;
#pragma unroll
    for (int d = 16; d; d >>= 1) v += __shfl_down_sync(0xffffffffu, v, d);
    if ((t & 31) == 0) red[t >> 5] = v;
    __syncthreads();
    if (t < 8) {
        int s = red[t];
#pragma unroll
        for (int d = 4; d; d >>= 1) s += __shfl_down_sync(0xffu, s, d);
        if (t == 0) g_partial[b] = s;
    }
}

// ---------------- 2b: full scan (partials scanned redundantly per block) -----
__global__ void scanC_kernel() {
    __shared__ int ws[8];
    __shared__ int spart[NBLK];
    int b = blockIdx.x, t = threadIdx.x;
    int lane = t & 31, w = t >> 5;

    {   // exclusive scan of the 196 block sums (every block redundantly)
        int pv = (t < NBLK) ? g_partial[t] : 0;
        int xv = pv;
#pragma unroll
        for (int d = 1; d < 32; d <<= 1) {
            int u = __shfl_up_sync(0xffffffffu, xv, d);
            if (lane >= d) xv += u;
        }
        if (lane == 31) ws[w] = xv;
        __syncthreads();
        if (w == 0 && lane < 8) {
            int y = ws[lane];
#pragma unroll
            for (int d = 1; d < 8; d <<= 1) {
                int u = __shfl_up_sync(0xffu, y, d);
                if (lane >= d) y += u;
            }
            ws[lane] = y;
        }
        __syncthreads();
        int pincl = xv + (w ? ws[w - 1] : 0);
        if (t < NBLK) spart[t] = pincl - pv;
        __syncthreads();
    }

    int i = b * 256 + t;
    int v = (i < NN) ? g_cnt[i] : 0;
    int xv = v;
#pragma unroll
    for (int d = 1; d < 32; d <<= 1) {
        int u = __shfl_up_sync(0xffffffffu, xv, d);
        if (lane >= d) xv += u;
    }
    if (lane == 31) ws[w] = xv;
    __syncthreads();
    if (w == 0 && lane < 8) {
        int y = ws[lane];
#pragma unroll
        for (int d = 1; d < 8; d <<= 1) {
            int u = __shfl_up_sync(0xffu, y, d);
            if (lane >= d) y += u;
        }
        ws[lane] = y;
    }
    __syncthreads();
    int excl = xv - v + (w ? ws[w - 1] : 0) + spart[b];
    if (i < NN) g_rowstart[i] = excl;
    if (b == 0 && t == 0) g_rowstart[NN] = EE;
}

// ---------------- 3) fill CSR column lists (atomic-free scatter) --------------
__global__ void fill_kernel() {
    int e = blockIdx.x * blockDim.x + threadIdx.x;
    if (e < EE)
        g_csr[g_rowstart[g_row[e]] + g_slot[e]] = g_col[e];
}

// ---------------- 4) tensor-core GEMM: [Y|Z] = x @ [W1;W2]^T ------------------
// fp32 emulated via bf16 split: a*b ~= ah*bh + ah*bl + al*bh
#define GM 128
#define GN 128
#define GK 32
#define APAD 2

__device__ __forceinline__ void mma_bf16(float c[4], const uint32_t a[4],
                                         uint32_t b0, uint32_t b1) {
    asm volatile(
        "mma.sync.aligned.m16n8k16.row.col.f32.bf16.bf16.f32 "
        "{%0,%1,%2,%3}, {%4,%5,%6,%7}, {%8,%9}, {%0,%1,%2,%3};"
        : "+f"(c[0]), "+f"(c[1]), "+f"(c[2]), "+f"(c[3])
        : "r"(a[0]), "r"(a[1]), "r"(a[2]), "r"(a[3]), "r"(b0), "r"(b1));
}

__global__ __launch_bounds__(256, 2)
void gemm_kernel(const float* __restrict__ x, const float* __restrict__ W) {
    __shared__ __nv_bfloat16 As_hi[GM][GK + APAD];
    __shared__ __nv_bfloat16 As_lo[GM][GK + APAD];
    __shared__ __nv_bfloat16 Bs_hi[GN][GK + APAD];
    __shared__ __nv_bfloat16 Bs_lo[GN][GK + APAD];

    int t = threadIdx.x;
    int block_m = blockIdx.x * GM;
    int half = blockIdx.y;
    int wid = t >> 5, lane = t & 31;
    int wm = (wid & 3) * 32;
    int wn = (wid >> 2) * 64;
    int g = lane >> 2, tig = lane & 3;

    float acc[2][8][4];
#pragma unroll
    for (int mi = 0; mi < 2; mi++)
#pragma unroll
        for (int ni = 0; ni < 8; ni++)
#pragma unroll
            for (int q = 0; q < 4; q++) acc[mi][ni][q] = 0.f;

    const float* wbase = W + (half ? DD : 0);

    for (int k0 = 0; k0 < DD; k0 += GK) {
#pragma unroll
        for (int i = 0; i < 4; i++) {
            int lin = t + i * 256;
            int row = lin >> 3;
            int kq = (lin & 7) * 4;
            int grow = block_m + row;
            float4 v = make_float4(0.f, 0.f, 0.f, 0.f);
            if (grow < NN)
                v = *(const float4*)(x + (size_t)grow * DD + k0 + kq);
            float vv[4] = {v.x, v.y, v.z, v.w};
#pragma unroll
            for (int q = 0; q < 4; q++) {
                __nv_bfloat16 h = __float2bfloat16(vv[q]);
                As_hi[row][kq + q] = h;
                As_lo[row][kq + q] = __float2bfloat16(vv[q] - __bfloat162float(h));
            }
        }
#pragma unroll
        for (int i = 0; i < 4; i++) {
            int lin = t + i * 256;
            int j = lin >> 3;
            int kq = (lin & 7) * 4;
            float4 v = *(const float4*)(wbase + (size_t)j * KK + k0 + kq);
            float vv[4] = {v.x, v.y, v.z, v.w};
#pragma unroll
            for (int q = 0; q < 4; q++) {
                __nv_bfloat16 h = __float2bfloat16(vv[q]);
                Bs_hi[j][kq + q] = h;
                Bs_lo[j][kq + q] = __float2bfloat16(vv[q] - __bfloat162float(h));
            }
        }
        __syncthreads();

#pragma unroll
        for (int kk = 0; kk < GK; kk += 16) {
            uint32_t ahi[2][4], alo[2][4];
#pragma unroll
            for (int mi = 0; mi < 2; mi++) {
                int r0 = wm + mi * 16 + g;
                int r1 = r0 + 8;
                int c0 = kk + 2 * tig;
                int c1 = c0 + 8;
                ahi[mi][0] = *(const uint32_t*)&As_hi[r0][c0];
                ahi[mi][1] = *(const uint32_t*)&As_hi[r1][c0];
                ahi[mi][2] = *(const uint32_t*)&As_hi[r0][c1];
                ahi[mi][3] = *(const uint32_t*)&As_hi[r1][c1];
                alo[mi][0] = *(const uint32_t*)&As_lo[r0][c0];
                alo[mi][1] = *(const uint32_t*)&As_lo[r1][c0];
                alo[mi][2] = *(const uint32_t*)&As_lo[r0][c1];
                alo[mi][3] = *(const uint32_t*)&As_lo[r1][c1];
            }
#pragma unroll
            for (int ni = 0; ni < 8; ni++) {
                int n = wn + ni * 8 + g;
                int c0 = kk + 2 * tig;
                int c1 = c0 + 8;
                uint32_t bh0 = *(const uint32_t*)&Bs_hi[n][c0];
                uint32_t bh1 = *(const uint32_t*)&Bs_hi[n][c1];
                uint32_t bl0 = *(const uint32_t*)&Bs_lo[n][c0];
                uint32_t bl1 = *(const uint32_t*)&Bs_lo[n][c1];
#pragma unroll
                for (int mi = 0; mi < 2; mi++) {
                    mma_bf16(acc[mi][ni], ahi[mi], bh0, bh1);
                    mma_bf16(acc[mi][ni], ahi[mi], bl0, bl1);
                    mma_bf16(acc[mi][ni], alo[mi], bh0, bh1);
                }
            }
        }
        __syncthreads();
    }

    if (half) {
        // Z: fp16 output
#pragma unroll
        for (int mi = 0; mi < 2; mi++) {
#pragma unroll
            for (int ni = 0; ni < 8; ni++) {
                int r0 = block_m + wm + mi * 16 + g;
                int r1 = r0 + 8;
                int n = wn + ni * 8 + 2 * tig;
                if (r0 < NN)
                    *(__half2*)(g_Z + (size_t)r0 * DD + n) =
                        __floats2half2_rn(acc[mi][ni][0], acc[mi][ni][1]);
                if (r1 < NN)
                    *(__half2*)(g_Z + (size_t)r1 * DD + n) =
                        __floats2half2_rn(acc[mi][ni][2], acc[mi][ni][3]);
            }
        }
    } else {
        // Y: fp32 output
#pragma unroll
        for (int mi = 0; mi < 2; mi++) {
#pragma unroll
            for (int ni = 0; ni < 8; ni++) {
                int r0 = block_m + wm + mi * 16 + g;
                int r1 = r0 + 8;
                int n = wn + ni * 8 + 2 * tig;
                if (r0 < NN)
                    *(float2*)(g_Y + (size_t)r0 * DD + n) =
                        make_float2(acc[mi][ni][0], acc[mi][ni][1]);
                if (r1 < NN)
                    *(float2*)(g_Y + (size_t)r1 * DD + n) =
                        make_float2(acc[mi][ni][2], acc[mi][ni][3]);
            }
        }
    }
}

// ---------------- 5) fused gather + epilogue ----------------------------------
// out[node] = relu( Y[node] + b + (sum_{c in nbrs} Z_fp16[c]) / (cnt + 1e-8) )
// lane handles 4 columns; per row-iteration each lane loads one uint2 (4 halves
// = 8B); warp covers the full 256B row, coalesced.
__global__ void final_kernel(const float* __restrict__ b, float* __restrict__ out) {
    int gtid = blockIdx.x * blockDim.x + threadIdx.x;
    int node = gtid >> 5;
    int lane = gtid & 31;
    if (node >= NN) return;
    int s0 = g_rowstart[node];
    int s1 = g_rowstart[node + 1];
    float4 acc = make_float4(0.f, 0.f, 0.f, 0.f);
    int c = (s0 < s1) ? g_csr[s0] : 0;
    for (int j = s0; j < s1; j++) {
        int cn = (j + 1 < s1) ? g_csr[j + 1] : 0;
        uint2 raw = *(const uint2*)(g_Z + (size_t)c * DD + lane * 4);
        float2 p0 = __half22float2(*(__half2*)&raw.x);
        float2 p1 = __half22float2(*(__half2*)&raw.y);
        acc.x += p0.x; acc.y += p0.y; acc.z += p1.x; acc.w += p1.y;
        c = cn;
    }
    float inv = 1.0f / ((float)(s1 - s0) + 1e-8f);
    float4 y  = *(const float4*)(g_Y + (size_t)node * DD + lane * 4);
    float4 bb = *(const float4*)(b + lane * 4);
    float4 o;
    o.x = fmaxf(y.x + bb.x + acc.x * inv, 0.f);
    o.y = fmaxf(y.y + bb.y + acc.y * inv, 0.f);
    o.z = fmaxf(y.z + bb.z + acc.z * inv, 0.f);
    o.w = fmaxf(y.w + bb.w + acc.w * inv, 0.f);
    *(float4*)(out + (size_t)node * DOUT + lane * 4) = o;
}

// ---------------- launch ------------------------------------------------------
extern "C" void kernel_launch(void* const* d_in, const int* in_sizes, int n_in,
                              void* d_out, int out_size) {
    const float* x   = (const float*)d_in[0];
    const void*  ei  = d_in[1];
    const float* W   = (const float*)d_in[2];
    const float* b   = (const float*)d_in[3];
    float*       out = (float*)d_out;

    cudaStream_t s1;
    cudaEvent_t  e_fork, e_join;
    cudaStreamCreateWithFlags(&s1, cudaStreamNonBlocking);
    cudaEventCreateWithFlags(&e_fork, cudaEventDisableTiming);
    cudaEventCreateWithFlags(&e_join, cudaEventDisableTiming);

    cudaEventRecord(e_fork, 0);
    cudaStreamWaitEvent(s1, e_fork, 0);

    // CSR branch (side stream)
    zero_kernel<<<(NN + 255) / 256, 256, 0, s1>>>();
    decode_hist_kernel<<<(EE + 255) / 256, 256, 0, s1>>>(ei);
    scanA_kernel<<<NBLK, 256, 0, s1>>>();
    scanC_kernel<<<NBLK, 256, 0, s1>>>();
    fill_kernel<<<(EE + 255) / 256, 256, 0, s1>>>();
    cudaEventRecord(e_join, s1);

    // GEMM branch (main stream) — overlaps CSR build
    dim3 ggrid((NN + GM - 1) / GM, 2);
    gemm_kernel<<<ggrid, 256>>>(x, W);

    cudaStreamWaitEvent(0, e_join, 0);
    final_kernel<<<(NN * 32 + 255) / 256, 256>>>(b, out);
}

// round 7
// speedup vs baseline: 3.6924x; 1.0119x over previous
#include <cuda_runtime.h>
#include <cuda_bf16.h>
#include <cuda_fp16.h>
#include <cstdint>

#define NN 50000
#define EE 640000
#define DD 128          // feature dim
#define KK 256          // 2*DD
#define DOUT 128
#define CAP 80          // max neighbors per node (Poisson(12.8): P(>=80) ~ 1e-45)

// ---------------- scratch (static device globals; no allocation) -------------
__device__ float  g_Y[(size_t)NN * DD];     // x @ W1^T   fp32 (25.6 MB)
__device__ __half g_Z[(size_t)NN * DD];     // x @ W2^T   fp16 (12.8 MB)
__device__ int    g_bucket[(size_t)NN * CAP];  // adjacency buckets (16 MB)
__device__ int    g_cnt[NN];

// ---------------- 0) zero counters -------------------------------------------
__global__ void zero_kernel() {
    int i = blockIdx.x * blockDim.x + threadIdx.x;
    if (i < NN) g_cnt[i] = 0;
}

// ---------------- 1) decode edge index + bucket insert (fused) ----------------
// int64 little-endian with values < 50000 => odd 32-bit words all zero.
__global__ void decode_bucket_kernel(const void* __restrict__ ei) {
    const int* ei32 = (const int*)ei;
    int t = threadIdx.x;
    int accw = ei32[2 * t + 1] | ei32[2 * (t + 256) + 1];
    int is32 = __syncthreads_or(accw);      // nonzero -> int32 indices

    int e = blockIdx.x * blockDim.x + t;
    if (e >= EE) return;
    int r, c;
    if (!is32) {
        const long long* p = (const long long*)ei;
        r = (int)p[e];
        c = (int)p[(size_t)EE + e];
    } else {
        r = ei32[e];
        c = ei32[EE + e];
    }
    r = min(max(r, 0), NN - 1);
    c = min(max(c, 0), NN - 1);
    int slot = atomicAdd(&g_cnt[r], 1);
    if (slot < CAP)
        g_bucket[(size_t)r * CAP + slot] = c;
}

// ---------------- 2) tensor-core GEMM: [Y|Z] = x @ [W1;W2]^T ------------------
// fp32 emulated via bf16 split: a*b ~= ah*bh + ah*bl + al*bh
#define GM 128
#define GN 128
#define GK 32
#define APAD 2

__device__ __forceinline__ void mma_bf16(float c[4], const uint32_t a[4],
                                         uint32_t b0, uint32_t b1) {
    asm volatile(
        "mma.sync.aligned.m16n8k16.row.col.f32.bf16.bf16.f32 "
        "{%0,%1,%2,%3}, {%4,%5,%6,%7}, {%8,%9}, {%0,%1,%2,%3};"
        : "+f"(c[0]), "+f"(c[1]), "+f"(c[2]), "+f"(c[3])
        : "r"(a[0]), "r"(a[1]), "r"(a[2]), "r"(a[3]), "r"(b0), "r"(b1));
}

__global__ __launch_bounds__(256, 2)
void gemm_kernel(const float* __restrict__ x, const float* __restrict__ W) {
    __shared__ __nv_bfloat16 As_hi[GM][GK + APAD];
    __shared__ __nv_bfloat16 As_lo[GM][GK + APAD];
    __shared__ __nv_bfloat16 Bs_hi[GN][GK + APAD];
    __shared__ __nv_bfloat16 Bs_lo[GN][GK + APAD];

    int t = threadIdx.x;
    int block_m = blockIdx.x * GM;
    int half = blockIdx.y;
    int wid = t >> 5, lane = t & 31;
    int wm = (wid & 3) * 32;
    int wn = (wid >> 2) * 64;
    int g = lane >> 2, tig = lane & 3;

    float acc[2][8][4];
#pragma unroll
    for (int mi = 0; mi < 2; mi++)
#pragma unroll
        for (int ni = 0; ni < 8; ni++)
#pragma unroll
            for (int q = 0; q < 4; q++) acc[mi][ni][q] = 0.f;

    const float* wbase = W + (half ? DD : 0);

    for (int k0 = 0; k0 < DD; k0 += GK) {
#pragma unroll
        for (int i = 0; i < 4; i++) {
            int lin = t + i * 256;
            int row = lin >> 3;
            int kq = (lin & 7) * 4;
            int grow = block_m + row;
            float4 v = make_float4(0.f, 0.f, 0.f, 0.f);
            if (grow < NN)
                v = *(const float4*)(x + (size_t)grow * DD + k0 + kq);
            float vv[4] = {v.x, v.y, v.z, v.w};
#pragma unroll
            for (int q = 0; q < 4; q++) {
                __nv_bfloat16 h = __float2bfloat16(vv[q]);
                As_hi[row][kq + q] = h;
                As_lo[row][kq + q] = __float2bfloat16(vv[q] - __bfloat162float(h));
            }
        }
#pragma unroll
        for (int i = 0; i < 4; i++) {
            int lin = t + i * 256;
            int j = lin >> 3;
            int kq = (lin & 7) * 4;
            float4 v = *(const float4*)(wbase + (size_t)j * KK + k0 + kq);
            float vv[4] = {v.x, v.y, v.z, v.w};
#pragma unroll
            for (int q = 0; q < 4; q++) {
                __nv_bfloat16 h = __float2bfloat16(vv[q]);
                Bs_hi[j][kq + q] = h;
                Bs_lo[j][kq + q] = __float2bfloat16(vv[q] - __bfloat162float(h));
            }
        }
        __syncthreads();

#pragma unroll
        for (int kk = 0; kk < GK; kk += 16) {
            uint32_t ahi[2][4], alo[2][4];
#pragma unroll
            for (int mi = 0; mi < 2; mi++) {
                int r0 = wm + mi * 16 + g;
                int r1 = r0 + 8;
                int c0 = kk + 2 * tig;
                int c1 = c0 + 8;
                ahi[mi][0] = *(const uint32_t*)&As_hi[r0][c0];
                ahi[mi][1] = *(const uint32_t*)&As_hi[r1][c0];
                ahi[mi][2] = *(const uint32_t*)&As_hi[r0][c1];
                ahi[mi][3] = *(const uint32_t*)&As_hi[r1][c1];
                alo[mi][0] = *(const uint32_t*)&As_lo[r0][c0];
                alo[mi][1] = *(const uint32_t*)&As_lo[r1][c0];
                alo[mi][2] = *(const uint32_t*)&As_lo[r0][c1];
                alo[mi][3] = *(const uint32_t*)&As_lo[r1][c1];
            }
#pragma unroll
            for (int ni = 0; ni < 8; ni++) {
                int n = wn + ni * 8 + g;
                int c0 = kk + 2 * tig;
                int c1 = c0 + 8;
                uint32_t bh0 = *(const uint32_t*)&Bs_hi[n][c0];
                uint32_t bh1 = *(const uint32_t*)&Bs_hi[n][c1];
                uint32_t bl0 = *(const uint32_t*)&Bs_lo[n][c0];
                uint32_t bl1 = *(const uint32_t*)&Bs_lo[n][c1];
#pragma unroll
                for (int mi = 0; mi < 2; mi++) {
                    mma_bf16(acc[mi][ni], ahi[mi], bh0, bh1);
                    mma_bf16(acc[mi][ni], ahi[mi], bl0, bl1);
                    mma_bf16(acc[mi][ni], alo[mi], bh0, bh1);
                }
            }
        }
        __syncthreads();
    }

    if (half) {
#pragma unroll
        for (int mi = 0; mi < 2; mi++) {
#pragma unroll
            for (int ni = 0; ni < 8; ni++) {
                int r0 = block_m + wm + mi * 16 + g;
                int r1 = r0 + 8;
                int n = wn + ni * 8 + 2 * tig;
                if (r0 < NN)
                    *(__half2*)(g_Z + (size_t)r0 * DD + n) =
                        __floats2half2_rn(acc[mi][ni][0], acc[mi][ni][1]);
                if (r1 < NN)
                    *(__half2*)(g_Z + (size_t)r1 * DD + n) =
                        __floats2half2_rn(acc[mi][ni][2], acc[mi][ni][3]);
            }
        }
    } else {
#pragma unroll
        for (int mi = 0; mi < 2; mi++) {
#pragma unroll
            for (int ni = 0; ni < 8; ni++) {
                int r0 = block_m + wm + mi * 16 + g;
                int r1 = r0 + 8;
                int n = wn + ni * 8 + 2 * tig;
                if (r0 < NN)
                    *(float2*)(g_Y + (size_t)r0 * DD + n) =
                        make_float2(acc[mi][ni][0], acc[mi][ni][1]);
                if (r1 < NN)
                    *(float2*)(g_Y + (size_t)r1 * DD + n) =
                        make_float2(acc[mi][ni][2], acc[mi][ni][3]);
            }
        }
    }
}

// ---------------- 3) fused gather + epilogue ----------------------------------
// out[node] = relu( Y[node] + b + (sum_{c in bucket} Z_fp16[c]) / (cnt + 1e-8) )
__global__ void final_kernel(const float* __restrict__ b, float* __restrict__ out) {
    int gtid = blockIdx.x * blockDim.x + threadIdx.x;
    int node = gtid >> 5;
    int lane = gtid & 31;
    if (node >= NN) return;
    int cnt = g_cnt[node];
    int m = min(cnt, CAP);
    const int* bucket = g_bucket + (size_t)node * CAP;
    float4 acc = make_float4(0.f, 0.f, 0.f, 0.f);
    int c = (m > 0) ? bucket[0] : 0;
    for (int j = 0; j < m; j++) {
        int cn = (j + 1 < m) ? bucket[j + 1] : 0;   // prefetch next col idx
        uint2 raw = *(const uint2*)(g_Z + (size_t)c * DD + lane * 4);
        float2 p0 = __half22float2(*(__half2*)&raw.x);
        float2 p1 = __half22float2(*(__half2*)&raw.y);
        acc.x += p0.x; acc.y += p0.y; acc.z += p1.x; acc.w += p1.y;
        c = cn;
    }
    float inv = 1.0f / ((float)cnt + 1e-8f);
    float4 y  = *(const float4*)(g_Y + (size_t)node * DD + lane * 4);
    float4 bb = *(const float4*)(b + lane * 4);
    float4 o;
    o.x = fmaxf(y.x + bb.x + acc.x * inv, 0.f);
    o.y = fmaxf(y.y + bb.y + acc.y * inv, 0.f);
    o.z = fmaxf(y.z + bb.z + acc.z * inv, 0.f);
    o.w = fmaxf(y.w + bb.w + acc.w * inv, 0.f);
    *(float4*)(out + (size_t)node * DOUT + lane * 4) = o;
}

// ---------------- launch ------------------------------------------------------
// Fork: bucket build (side stream) overlaps the GEMM (main stream); join
// before the final gather. Handles are leaked intentionally (kernel_launch is
// invoked only for correctness + capture; replays re-execute the graph).
extern "C" void kernel_launch(void* const* d_in, const int* in_sizes, int n_in,
                              void* d_out, int out_size) {
    const float* x   = (const float*)d_in[0];
    const void*  ei  = d_in[1];
    const float* W   = (const float*)d_in[2];
    const float* b   = (const float*)d_in[3];
    float*       out = (float*)d_out;

    cudaStream_t s1;
    cudaEvent_t  e_fork, e_join;
    cudaStreamCreateWithFlags(&s1, cudaStreamNonBlocking);
    cudaEventCreateWithFlags(&e_fork, cudaEventDisableTiming);
    cudaEventCreateWithFlags(&e_join, cudaEventDisableTiming);

    cudaEventRecord(e_fork, 0);
    cudaStreamWaitEvent(s1, e_fork, 0);

    // adjacency branch (side stream)
    zero_kernel<<<(NN + 255) / 256, 256, 0, s1>>>();
    decode_bucket_kernel<<<(EE + 255) / 256, 256, 0, s1>>>(ei);
    cudaEventRecord(e_join, s1);

    // GEMM branch (main stream) — overlaps bucket build
    dim3 ggrid((NN + GM - 1) / GM, 2);
    gemm_kernel<<<ggrid, 256>>>(x, W);

    cudaStreamWaitEvent(0, e_join, 0);
    final_kernel<<<(NN * 32 + 255) / 256, 256>>>(b, out);
}